// round 1
// baseline (speedup 1.0000x reference)
#include <cuda_runtime.h>
#include <math.h>

#define Bn 64
#define Tn 512
#define Hn 768
#define Ln 25

// scratch (device globals — no allocation allowed)
__device__ float g_em[Bn * Tn * Ln];   // emissions [B,T,L]
__device__ float g_llh[Bn];

// ---------------------------------------------------------------------------
// Kernel 1: emissions = X @ W + b
// 256 rows/block, 128 threads (2 rows/thread), K-chunks of 32 staged in smem.
// ---------------------------------------------------------------------------
__global__ __launch_bounds__(128) void gemm_kernel(const float* __restrict__ X,
                                                   const float* __restrict__ W,
                                                   const float* __restrict__ bias) {
    __shared__ float Xs[256 * 33];   // padded to 33 to kill bank conflicts
    __shared__ float Ws[32 * 25];

    const int tid  = threadIdx.x;
    const int row0 = blockIdx.x * 256;

    float acc0[Ln], acc1[Ln];
#pragma unroll
    for (int l = 0; l < Ln; ++l) { float bv = bias[l]; acc0[l] = bv; acc1[l] = bv; }

    for (int h0 = 0; h0 < Hn; h0 += 32) {
        // load W chunk [32 x 25] (contiguous)
        for (int i = tid; i < 32 * 25; i += 128) Ws[i] = W[h0 * 25 + i];
        // load X chunk [256 rows x 32 k] — each warp reads one 128B row segment
#pragma unroll 8
        for (int it = 0; it < 64; ++it) {
            int i  = it * 128 + tid;
            int r  = i >> 5;
            int kk = i & 31;
            Xs[r * 33 + kk] = X[(size_t)(row0 + r) * Hn + h0 + kk];
        }
        __syncthreads();

#pragma unroll 4
        for (int kk = 0; kk < 32; ++kk) {
            float x0 = Xs[tid * 33 + kk];
            float x1 = Xs[(tid + 128) * 33 + kk];
#pragma unroll
            for (int l = 0; l < Ln; ++l) {
                float w = Ws[kk * 25 + l];
                acc0[l] = fmaf(x0, w, acc0[l]);
                acc1[l] = fmaf(x1, w, acc1[l]);
            }
        }
        __syncthreads();
    }

    float* o0 = g_em + (size_t)(row0 + tid) * Ln;
    float* o1 = g_em + (size_t)(row0 + tid + 128) * Ln;
#pragma unroll
    for (int l = 0; l < Ln; ++l) { o0[l] = acc0[l]; o1[l] = acc1[l]; }
}

// ---------------------------------------------------------------------------
// Kernel 2: CRF log-likelihood per batch. One warp per batch.
// Forward algorithm in the exp (linear) domain:
//   p_{t} = (p_{t-1}^T * exp(trans)) .* exp(em_t),   running log-scale C,
//   rescale by sum every 8 steps for fp32 range safety.
// ---------------------------------------------------------------------------
__global__ __launch_bounds__(32) void crf_kernel(const int* __restrict__ mask,
                                                 const int* __restrict__ labels,
                                                 const float* __restrict__ trans,
                                                 const float* __restrict__ start_t,
                                                 const float* __restrict__ end_t) {
    const int b  = blockIdx.x;
    const int j  = threadIdx.x;
    const int jc = (j < Ln) ? j : (Ln - 1);   // clamp for safe loads on lanes >= 25

    const float* emb = g_em + (size_t)b * Tn * Ln;
    const int*   mb  = mask + b * Tn;
    const int*   lb  = labels + b * Tn;

    __shared__ int smask[Tn];
    for (int t = j; t < Tn; t += 32) smask[t] = mb[t];
    __syncwarp();

    // ---- numerator (parallel over t across the warp) ----
    float numv = 0.f;
    int   msum = 0;
    for (int t = j; t < Tn; t += 32) {
        int m = smask[t];
        msum += m;
        int lt = lb[t];
        if (t == 0) {
            numv += start_t[lt] + emb[lt];
        } else if (m) {
            numv += trans[lb[t - 1] * Ln + lt] + emb[t * Ln + lt];
        }
    }
#pragma unroll
    for (int off = 16; off; off >>= 1) {
        numv += __shfl_xor_sync(0xffffffffu, numv, off);
        msum += __shfl_xor_sync(0xffffffffu, msum, off);
    }

    // ---- precompute exp(trans[:, j]) (column j held by lane j) ----
    float et[Ln];
#pragma unroll
    for (int i = 0; i < Ln; ++i) et[i] = expf(trans[i * Ln + jc]);
    const float eend = expf(end_t[jc]);

    // ---- forward scan ----
    float p = (j < Ln) ? expf(start_t[jc] + emb[jc]) : 0.f;
    float C = 0.f;

    float emt = emb[Ln + jc];   // prefetch row t=1
    for (int t = 1; t < Tn; ++t) {
        float eem = expf(emt);
        if (t + 1 < Tn) emt = emb[(t + 1) * Ln + jc];   // prefetch next row
        int m = smask[t];

        float q0 = 0.f, q1 = 0.f, q2 = 0.f, q3 = 0.f, q4 = 0.f;
#pragma unroll
        for (int i = 0; i < Ln; i += 5) {
            q0 = fmaf(__shfl_sync(0xffffffffu, p, i + 0), et[i + 0], q0);
            q1 = fmaf(__shfl_sync(0xffffffffu, p, i + 1), et[i + 1], q1);
            q2 = fmaf(__shfl_sync(0xffffffffu, p, i + 2), et[i + 2], q2);
            q3 = fmaf(__shfl_sync(0xffffffffu, p, i + 3), et[i + 3], q3);
            q4 = fmaf(__shfl_sync(0xffffffffu, p, i + 4), et[i + 4], q4);
        }
        float q  = ((q0 + q1) + (q2 + q3)) + q4;
        float pn = q * eem;
        if (j < Ln && m) p = pn;

        if ((t & 7) == 7) {   // periodic renormalization (fp32 range safety)
            float s = p;
#pragma unroll
            for (int off = 16; off; off >>= 1) s += __shfl_xor_sync(0xffffffffu, s, off);
            p = p / s;
            C += logf(s);
        }
    }

    float tot = (j < Ln) ? p * eend : 0.f;
#pragma unroll
    for (int off = 16; off; off >>= 1) tot += __shfl_xor_sync(0xffffffffu, tot, off);
    float denom = C + logf(tot);

    if (j == 0) {
        int   last      = msum - 1;
        float num_final = numv + end_t[lb[last]];
        g_llh[b] = num_final - denom;
    }
}

// ---------------------------------------------------------------------------
// Kernel 3: out = -mean(llh)
// ---------------------------------------------------------------------------
__global__ __launch_bounds__(32) void finalize_kernel(float* __restrict__ out) {
    int tid = threadIdx.x;
    float s = g_llh[tid] + g_llh[tid + 32];
#pragma unroll
    for (int off = 16; off; off >>= 1) s += __shfl_xor_sync(0xffffffffu, s, off);
    if (tid == 0) out[0] = -s * (1.0f / 64.0f);
}

// ---------------------------------------------------------------------------
extern "C" void kernel_launch(void* const* d_in, const int* in_sizes, int n_in,
                              void* d_out, int out_size) {
    const float* X      = (const float*)d_in[0];   // encoder_logits [B,T,H]
    const int*   mask   = (const int*)  d_in[1];   // attention_mask [B,T]
    const int*   labels = (const int*)  d_in[2];   // labels [B,T]
    const float* W      = (const float*)d_in[3];   // W_em [H,L]
    const float* bias   = (const float*)d_in[4];   // b_em [L]
    const float* trans  = (const float*)d_in[5];   // trans [L,L]
    const float* st     = (const float*)d_in[6];   // start_t [L]
    const float* en     = (const float*)d_in[7];   // end_t [L]
    float* out = (float*)d_out;

    gemm_kernel<<<(Bn * Tn) / 256, 128>>>(X, W, bias);
    crf_kernel<<<Bn, 32>>>(mask, labels, trans, st, en);
    finalize_kernel<<<1, 32>>>(out);
}

// round 2
// speedup vs baseline: 2.3792x; 2.3792x over previous
#include <cuda_runtime.h>
#include <math.h>

#define Bn 64
#define Tn 512
#define Hn 768
#define Ln 25

__device__ float g_em[Bn * Tn * Ln];   // emissions [B,T,L]
__device__ float g_llh[Bn];

__device__ __forceinline__ unsigned long long fma2(unsigned long long a,
                                                   unsigned long long b,
                                                   unsigned long long c) {
    unsigned long long d;
    asm("fma.rn.f32x2 %0, %1, %2, %3;" : "=l"(d) : "l"(a), "l"(b), "l"(c));
    return d;
}

// ---------------------------------------------------------------------------
// Kernel 1: emissions = X @ W + b
// 256 blocks x 256 threads. 128 rows/block, 2 threads per row (K split in 2).
// Whole W resident in smem as [768][26] (pad->8B alignment for LDS.64).
// Inner loop: packed fma.rn.f32x2, 12 pairs + 1 scalar per k.
// ---------------------------------------------------------------------------
__global__ __launch_bounds__(256) void gemm_kernel(const float* __restrict__ X,
                                                   const float* __restrict__ W,
                                                   const float* __restrict__ bias,
                                                   float* __restrict__ em) {
    extern __shared__ float Ws[];          // 768*26 floats = 79872 B
    __shared__ float bs[Ln];

    const int tid = threadIdx.x;

    // stage W: Ws[k*26 + l] = W[k*25 + l]
    for (int i = tid; i < Hn * Ln; i += 256) {
        int k = i / Ln;
        int l = i - k * Ln;
        Ws[k * 26 + l] = W[i];
    }
    if (tid < Ln) bs[tid] = bias[tid];
    __syncthreads();

    const int half = tid >> 7;             // which K half
    const int rloc = tid & 127;
    const int row  = blockIdx.x * 128 + rloc;

    unsigned long long acc2[12];
    float acc24 = 0.f;
#pragma unroll
    for (int m = 0; m < 12; ++m) acc2[m] = 0ull;

    const float4* xp = (const float4*)(X + (size_t)row * Hn + half * 384);
    const int kofs = half * 384;

#pragma unroll 2
    for (int k4 = 0; k4 < 96; ++k4) {
        float4 xv = xp[k4];
        float xs[4] = {xv.x, xv.y, xv.z, xv.w};
        int kbase = kofs + k4 * 4;
#pragma unroll
        for (int s = 0; s < 4; ++s) {
            int k = kbase + s;
            unsigned long long xx;
            asm("mov.b64 %0, {%1, %1};" : "=l"(xx) : "r"(__float_as_uint(xs[s])));
            const unsigned long long* wp =
                (const unsigned long long*)(Ws + k * 26);
#pragma unroll
            for (int m = 0; m < 12; ++m)
                acc2[m] = fma2(xx, wp[m], acc2[m]);
            acc24 = fmaf(xs[s], Ws[k * 26 + 24], acc24);
        }
    }

    // unpack accumulators
    float accf[Ln];
#pragma unroll
    for (int m = 0; m < 12; ++m) {
        unsigned int lo, hi;
        asm("mov.b64 {%0, %1}, %2;" : "=r"(lo), "=r"(hi) : "l"(acc2[m]));
        accf[2 * m]     = __uint_as_float(lo);
        accf[2 * m + 1] = __uint_as_float(hi);
    }
    accf[24] = acc24;

    __syncthreads();                        // done reading Ws; reuse as scratch
    if (half == 1) {
        float* dst = Ws + rloc * 26;
#pragma unroll
        for (int l = 0; l < Ln; ++l) dst[l] = accf[l];
    }
    __syncthreads();
    if (half == 0) {
        const float* src = Ws + rloc * 26;
        float* o = em + (size_t)row * Ln;
#pragma unroll
        for (int l = 0; l < Ln; ++l) o[l] = accf[l] + src[l] + bs[l];
    }
}

// ---------------------------------------------------------------------------
// Kernel 2: CRF log-likelihood, one warp per batch.
// Exp-domain forward scan; emissions staged into smem in 64-step chunks;
// renormalize every 16 steps.
// ---------------------------------------------------------------------------
__global__ __launch_bounds__(32) void crf_kernel(const int* __restrict__ mask,
                                                 const int* __restrict__ labels,
                                                 const float* __restrict__ trans,
                                                 const float* __restrict__ start_t,
                                                 const float* __restrict__ end_t,
                                                 const float* __restrict__ emB) {
    const int b  = blockIdx.x;
    const int j  = threadIdx.x;
    const int jc = (j < Ln) ? j : (Ln - 1);

    const float* emb = emB + (size_t)b * Tn * Ln;
    const int*   lb  = labels + b * Tn;

    __shared__ int   smask[Tn];
    __shared__ float ems[64 * Ln];          // one 64-step chunk

    for (int t = j; t < Tn; t += 32) smask[t] = mask[b * Tn + t];

    // ---- numerator (each lane only touches its own smask writes) ----
    float numv = 0.f;
    int   msum = 0;
    for (int t = j; t < Tn; t += 32) {
        int m = smask[t];
        msum += m;
        int lt = lb[t];
        if (t == 0) {
            numv += start_t[lt] + emb[lt];
        } else if (m) {
            numv += trans[lb[t - 1] * Ln + lt] + emb[t * Ln + lt];
        }
    }
#pragma unroll
    for (int off = 16; off; off >>= 1) {
        numv += __shfl_xor_sync(0xffffffffu, numv, off);
        msum += __shfl_xor_sync(0xffffffffu, msum, off);
    }

    // ---- precompute exp(trans[:, j]) held by lane j ----
    float et[Ln];
#pragma unroll
    for (int i = 0; i < Ln; ++i) et[i] = __expf(trans[i * Ln + jc]);
    const float eend = __expf(end_t[jc]);

    float p = 0.f, C = 0.f;

    for (int c = 0; c < 8; ++c) {
        __syncwarp();
        // stage 64 rows x 25 floats = 400 float4, coalesced
        const float4* src = (const float4*)(emb + c * 64 * Ln);
        float4*       dst = (float4*)ems;
        for (int i = j; i < 400; i += 32) dst[i] = src[i];
        __syncwarp();

        int tl0 = 0;
        if (c == 0) {
            p = (j < Ln) ? __expf(start_t[jc] + ems[jc]) : 0.f;
            tl0 = 1;
        }

        float emt = ems[tl0 * Ln + jc];
        for (int tl = tl0; tl < 64; ++tl) {
            float eem = __expf(emt);
            if (tl + 1 < 64) emt = ems[(tl + 1) * Ln + jc];
            int t = c * 64 + tl;
            int m = smask[t];

            float q0 = 0.f, q1 = 0.f, q2 = 0.f, q3 = 0.f, q4 = 0.f;
#pragma unroll
            for (int i = 0; i < Ln; i += 5) {
                q0 = fmaf(__shfl_sync(0xffffffffu, p, i + 0), et[i + 0], q0);
                q1 = fmaf(__shfl_sync(0xffffffffu, p, i + 1), et[i + 1], q1);
                q2 = fmaf(__shfl_sync(0xffffffffu, p, i + 2), et[i + 2], q2);
                q3 = fmaf(__shfl_sync(0xffffffffu, p, i + 3), et[i + 3], q3);
                q4 = fmaf(__shfl_sync(0xffffffffu, p, i + 4), et[i + 4], q4);
            }
            float pn = (((q0 + q1) + (q2 + q3)) + q4) * eem;
            if (j < Ln && m) p = pn;

            if ((t & 15) == 15) {            // periodic renormalization
                float s = p;
#pragma unroll
                for (int off = 16; off; off >>= 1)
                    s += __shfl_xor_sync(0xffffffffu, s, off);
                p = __fdividef(p, s);
                C += __logf(s);
            }
        }
    }

    float tot = (j < Ln) ? p * eend : 0.f;
#pragma unroll
    for (int off = 16; off; off >>= 1) tot += __shfl_xor_sync(0xffffffffu, tot, off);
    float denom = C + __logf(tot);

    if (j == 0) {
        int   last = msum - 1;
        g_llh[b] = (numv + end_t[lb[last]]) - denom;
    }
}

// ---------------------------------------------------------------------------
__global__ __launch_bounds__(32) void finalize_kernel(float* __restrict__ out) {
    int tid = threadIdx.x;
    float s = g_llh[tid] + g_llh[tid + 32];
#pragma unroll
    for (int off = 16; off; off >>= 1) s += __shfl_xor_sync(0xffffffffu, s, off);
    if (tid == 0) out[0] = -s * (1.0f / 64.0f);
}

// ---------------------------------------------------------------------------
extern "C" void kernel_launch(void* const* d_in, const int* in_sizes, int n_in,
                              void* d_out, int out_size) {
    const float* X      = (const float*)d_in[0];
    const int*   mask   = (const int*)  d_in[1];
    const int*   labels = (const int*)  d_in[2];
    const float* W      = (const float*)d_in[3];
    const float* bias   = (const float*)d_in[4];
    const float* trans  = (const float*)d_in[5];
    const float* st     = (const float*)d_in[6];
    const float* en     = (const float*)d_in[7];
    float* out = (float*)d_out;

    float* emp = nullptr;
    cudaGetSymbolAddress((void**)&emp, g_em);

    const int smem_bytes = Hn * 26 * sizeof(float);   // 79872
    cudaFuncSetAttribute(gemm_kernel,
                         cudaFuncAttributeMaxDynamicSharedMemorySize, smem_bytes);

    gemm_kernel<<<256, 256, smem_bytes>>>(X, W, bias, emp);
    crf_kernel<<<Bn, 32>>>(mask, labels, trans, st, en, emp);
    finalize_kernel<<<1, 32>>>(out);
}

// round 3
// speedup vs baseline: 2.6106x; 1.0973x over previous
#include <cuda_runtime.h>
#include <math.h>

#define Bn 64
#define Tn 512
#define Hn 768
#define Ln 25

typedef unsigned long long ull;

__device__ float g_em [Bn * Tn * Ln];   // emissions [B,T,L]
__device__ float g_eem[Bn * Tn * Ln];   // exp(emissions)
__device__ float g_llh[Bn];

__device__ __forceinline__ ull fma2(ull a, ull b, ull c) {
    ull d; asm("fma.rn.f32x2 %0, %1, %2, %3;" : "=l"(d) : "l"(a), "l"(b), "l"(c)); return d;
}
__device__ __forceinline__ ull add2(ull a, ull b) {
    ull d; asm("add.rn.f32x2 %0, %1, %2;" : "=l"(d) : "l"(a), "l"(b)); return d;
}
__device__ __forceinline__ ull dup2(float x) {
    ull d; asm("mov.b64 %0, {%1, %1};" : "=l"(d) : "r"(__float_as_uint(x))); return d;
}
__device__ __forceinline__ float lo2(ull a) {
    unsigned l, h; asm("mov.b64 {%0, %1}, %2;" : "=r"(l), "=r"(h) : "l"(a)); return __uint_as_float(l);
}
__device__ __forceinline__ float hi2(ull a) {
    unsigned l, h; asm("mov.b64 {%0, %1}, %2;" : "=r"(l), "=r"(h) : "l"(a)); return __uint_as_float(h);
}
__device__ __forceinline__ ull pack2(float l, float h) {
    ull d; asm("mov.b64 %0, {%1, %2};" : "=l"(d) : "r"(__float_as_uint(l)), "r"(__float_as_uint(h))); return d;
}

// ---------------------------------------------------------------------------
// Kernel 1: emissions = X @ W + b   (also writes exp(emissions))
// 256 blocks x 128 threads. Block = 128 rows, 2 K-halves (tid>>6), 2 rows/thread.
// K-chunks of 32 per half staged in smem (X 128x66 pad, W 64x26 pad).
// ---------------------------------------------------------------------------
__global__ __launch_bounds__(128) void gemm_kernel(const float* __restrict__ X,
                                                   const float* __restrict__ W,
                                                   const float* __restrict__ bias,
                                                   float* __restrict__ em,
                                                   float* __restrict__ eem) {
    __shared__ float Xs[128 * 66];
    __shared__ float Wc[64 * 26];
    __shared__ float bsm[32];

    const int tid  = threadIdx.x;
    const int half = tid >> 6;
    const int rt   = tid & 63;
    const int row0 = blockIdx.x * 128;

    if (tid < Ln) bsm[tid] = bias[tid];

    ull   acc0[12], acc1[12];
    float a24_0 = 0.f, a24_1 = 0.f;
#pragma unroll
    for (int m = 0; m < 12; ++m) { acc0[m] = 0ull; acc1[m] = 0ull; }

    for (int c = 0; c < 12; ++c) {
        __syncthreads();
        // stage X: 128 rows x 64 cols (cols 0-31: half0 k-strip, 32-63: half1)
#pragma unroll 8
        for (int it = 0; it < 64; ++it) {
            int i  = it * 128 + tid;
            int r  = i >> 6;
            int cc = i & 63;
            int kg = (cc < 32) ? (c * 32 + cc) : (352 + c * 32 + cc);
            Xs[r * 66 + cc] = X[(size_t)(row0 + r) * Hn + kg];
        }
        // stage W: 64 k-rows x 25 (pad 26)
        for (int i = tid; i < 64 * 25; i += 128) {
            int kk = i / 25;
            int l  = i - kk * 25;
            int kg = (kk < 32) ? (c * 32 + kk) : (352 + c * 32 + kk);
            Wc[kk * 26 + l] = W[kg * 25 + l];
        }
        __syncthreads();

        const float* x0 = Xs + rt * 66 + half * 32;
        const float* x1 = x0 + 64 * 66;
        const float* wb = Wc + half * 32 * 26;
#pragma unroll 4
        for (int kk = 0; kk < 32; ++kk) {
            float xa = x0[kk], xb = x1[kk];
            ull da = dup2(xa), db = dup2(xb);
            const ull* wp = (const ull*)(wb + kk * 26);
#pragma unroll
            for (int m = 0; m < 12; ++m) {
                ull w = wp[m];
                acc0[m] = fma2(da, w, acc0[m]);
                acc1[m] = fma2(db, w, acc1[m]);
            }
            float w24 = wb[kk * 26 + 24];
            a24_0 = fmaf(xa, w24, a24_0);
            a24_1 = fmaf(xb, w24, a24_1);
        }
    }

    float f0[Ln], f1[Ln];
#pragma unroll
    for (int m = 0; m < 12; ++m) {
        f0[2*m] = lo2(acc0[m]); f0[2*m+1] = hi2(acc0[m]);
        f1[2*m] = lo2(acc1[m]); f1[2*m+1] = hi2(acc1[m]);
    }
    f0[24] = a24_0; f1[24] = a24_1;

    __syncthreads();                 // Xs free -> reuse as combine scratch
    if (half == 1) {
        float* d0 = Xs + rt * 26;
        float* d1 = Xs + (rt + 64) * 26;
#pragma unroll
        for (int l = 0; l < Ln; ++l) { d0[l] = f0[l]; d1[l] = f1[l]; }
    }
    __syncthreads();
    if (half == 0) {
        const float* s0 = Xs + rt * 26;
        const float* s1 = Xs + (rt + 64) * 26;
        size_t r0 = (size_t)(row0 + rt) * Ln;
        size_t r1 = (size_t)(row0 + rt + 64) * Ln;
#pragma unroll
        for (int l = 0; l < Ln; ++l) {
            float v0 = f0[l] + s0[l] + bsm[l];
            float v1 = f1[l] + s1[l] + bsm[l];
            em[r0 + l] = v0;  eem[r0 + l] = __expf(v0);
            em[r1 + l] = v1;  eem[r1 + l] = __expf(v1);
        }
    }
}

// ---------------------------------------------------------------------------
// Kernel 2: CRF log-likelihood, one warp per batch.
// Exp-domain scan; state replicated via smem (STS + 7x LDS.128), 13 FFMA2/step.
// Branch-free exponent renorm every 16 steps via __reduce_max_sync.
// ---------------------------------------------------------------------------
#define CRF_STEP(TL, TG)                                                        \
    {                                                                           \
        pbuf[j] = p;                                                            \
        __syncwarp();                                                           \
        const ulonglong2* pb = (const ulonglong2*)pbuf;                         \
        ulonglong2 w0 = pb[0], w1 = pb[1], w2 = pb[2], w3 = pb[3];              \
        ulonglong2 w4 = pb[4], w5 = pb[5], w6 = pb[6];                          \
        ull A = fma2(w0.x, et2[0], 0ull);                                       \
        ull Bq = fma2(w0.y, et2[1], 0ull);                                      \
        ull Cq = fma2(w1.x, et2[2], 0ull);                                      \
        ull Dq = fma2(w1.y, et2[3], 0ull);                                      \
        A  = fma2(w2.x, et2[4], A);   Bq = fma2(w2.y, et2[5], Bq);              \
        Cq = fma2(w3.x, et2[6], Cq);  Dq = fma2(w3.y, et2[7], Dq);              \
        A  = fma2(w4.x, et2[8], A);   Bq = fma2(w4.y, et2[9], Bq);              \
        Cq = fma2(w5.x, et2[10], Cq); Dq = fma2(w5.y, et2[11], Dq);             \
        A  = fma2(w6.x, et2[12], A);                                            \
        A  = add2(A, Bq); Cq = add2(Cq, Dq); A = add2(A, Cq);                   \
        float q  = lo2(A) + hi2(A);                                             \
        float pn = q * ems[(TL) * Ln + jc];                                     \
        p = (lane_ok && smask[TG]) ? pn : p;                                    \
    }

#define CRF_RENORM                                                              \
    {                                                                           \
        unsigned mx = __reduce_max_sync(0xffffffffu, __float_as_uint(p));       \
        int e = (int)(mx >> 23);                                                \
        float sc = __uint_as_float((unsigned)(253 - e) << 23);  /* 2^(126-e) */ \
        p *= sc;                                                                \
        C += (float)(e - 126) * 0.6931471805599453f;                            \
    }

__global__ __launch_bounds__(32) void crf_kernel(const int* __restrict__ mask,
                                                 const int* __restrict__ labels,
                                                 const float* __restrict__ trans,
                                                 const float* __restrict__ start_t,
                                                 const float* __restrict__ end_t) {
    const int b  = blockIdx.x;
    const int j  = threadIdx.x;
    const int jc = (j < Ln) ? j : (Ln - 1);
    const bool lane_ok = (j < Ln);

    const float* emb  = g_em  + (size_t)b * Tn * Ln;
    const float* eemb = g_eem + (size_t)b * Tn * Ln;
    const int*   lb   = labels + b * Tn;

    __shared__ float pbuf[32];
    __shared__ float ems[64 * Ln];
    __shared__ int   smask[Tn];

    for (int t = j; t < Tn; t += 32) smask[t] = mask[b * Tn + t];

    // ---- numerator (lanes read only their own smask writes) ----
    float numv = 0.f; int msum = 0;
    for (int t = j; t < Tn; t += 32) {
        int m = smask[t];
        msum += m;
        int lt = lb[t];
        if (t == 0)      numv += start_t[lt] + emb[lt];
        else if (m)      numv += trans[lb[t - 1] * Ln + lt] + emb[t * Ln + lt];
    }
#pragma unroll
    for (int off = 16; off; off >>= 1) {
        numv += __shfl_xor_sync(0xffffffffu, numv, off);
        msum += __shfl_xor_sync(0xffffffffu, msum, off);
    }

    // ---- exp(trans) column pairs: et2[i] = (e^trans[2i][j], e^trans[2i+1][j]) ----
    ull et2[13];
#pragma unroll
    for (int i = 0; i < 13; ++i) {
        float lo = __expf(trans[(2 * i) * Ln + jc]);
        float hi = (2 * i + 1 < Ln) ? __expf(trans[(2 * i + 1) * Ln + jc]) : 0.f;
        et2[i] = pack2(lo, hi);
    }
    const float eend = __expf(end_t[jc]);

    float p = 0.f, C = 0.f;

    // ---- chunk 0 (peeled: init at t=0, 15-step first group) ----
    {
        __syncwarp();
        const float4* src = (const float4*)eemb;
        float4* dst = (float4*)ems;
#pragma unroll
        for (int i = 0; i < 13; ++i) { int idx = i * 32 + j; if (idx < 400) dst[idx] = src[idx]; }
        __syncwarp();

        p = lane_ok ? __expf(start_t[jc]) * ems[jc] : 0.f;

#pragma unroll
        for (int u = 1; u < 16; ++u) CRF_STEP(u, u)
        CRF_RENORM
#pragma unroll
        for (int g = 1; g < 4; ++g) {
#pragma unroll
            for (int u = 0; u < 16; ++u) CRF_STEP(g * 16 + u, g * 16 + u)
            CRF_RENORM
        }
    }
    // ---- chunks 1..7 ----
    for (int c = 1; c < 8; ++c) {
        __syncwarp();
        const float4* src = (const float4*)(eemb + c * 64 * Ln);
        float4* dst = (float4*)ems;
#pragma unroll
        for (int i = 0; i < 13; ++i) { int idx = i * 32 + j; if (idx < 400) dst[idx] = src[idx]; }
        __syncwarp();
        const int tbase = c * 64;
#pragma unroll
        for (int g = 0; g < 4; ++g) {
#pragma unroll
            for (int u = 0; u < 16; ++u) CRF_STEP(g * 16 + u, tbase + g * 16 + u)
            CRF_RENORM
        }
    }

    float tot = lane_ok ? p * eend : 0.f;
#pragma unroll
    for (int off = 16; off; off >>= 1) tot += __shfl_xor_sync(0xffffffffu, tot, off);
    float denom = C + __logf(tot);

    if (j == 0) {
        int last = msum - 1;
        g_llh[b] = (numv + end_t[lb[last]]) - denom;
    }
}

// ---------------------------------------------------------------------------
__global__ __launch_bounds__(32) void finalize_kernel(float* __restrict__ out) {
    int tid = threadIdx.x;
    float s = g_llh[tid] + g_llh[tid + 32];
#pragma unroll
    for (int off = 16; off; off >>= 1) s += __shfl_xor_sync(0xffffffffu, s, off);
    if (tid == 0) out[0] = -s * (1.0f / 64.0f);
}

// ---------------------------------------------------------------------------
extern "C" void kernel_launch(void* const* d_in, const int* in_sizes, int n_in,
                              void* d_out, int out_size) {
    const float* X      = (const float*)d_in[0];
    const int*   mask   = (const int*)  d_in[1];
    const int*   labels = (const int*)  d_in[2];
    const float* W      = (const float*)d_in[3];
    const float* bias   = (const float*)d_in[4];
    const float* trans  = (const float*)d_in[5];
    const float* st     = (const float*)d_in[6];
    const float* en     = (const float*)d_in[7];
    float* out = (float*)d_out;

    float *emp = nullptr, *eemp = nullptr;
    cudaGetSymbolAddress((void**)&emp,  g_em);
    cudaGetSymbolAddress((void**)&eemp, g_eem);

    gemm_kernel<<<256, 128>>>(X, W, bias, emp, eemp);
    crf_kernel<<<Bn, 32>>>(mask, labels, trans, st, en);
    finalize_kernel<<<1, 32>>>(out);
}

// round 5
// speedup vs baseline: 5.2393x; 2.0070x over previous
#include <cuda_runtime.h>
#include <math.h>
#include <stdint.h>

#define Bn 64
#define Tn 512
#define Hn 768
#define Ln 25

__device__ float g_em [Bn * Tn * Ln];
__device__ float g_eem[Bn * Tn * Ln];
__device__ float g_llh[Bn];
__device__ float g_wt [32 * Hn];        // W^T, zero-padded to 32 rows

typedef unsigned long long ull;

__device__ __forceinline__ ull fma2(ull a, ull b, ull c) {
    ull d; asm("fma.rn.f32x2 %0, %1, %2, %3;" : "=l"(d) : "l"(a), "l"(b), "l"(c)); return d;
}
__device__ __forceinline__ ull add2(ull a, ull b) {
    ull d; asm("add.rn.f32x2 %0, %1, %2;" : "=l"(d) : "l"(a), "l"(b)); return d;
}
__device__ __forceinline__ float lo2(ull a) {
    unsigned l, h; asm("mov.b64 {%0, %1}, %2;" : "=r"(l), "=r"(h) : "l"(a)); return __uint_as_float(l);
}
__device__ __forceinline__ float hi2(ull a) {
    unsigned l, h; asm("mov.b64 {%0, %1}, %2;" : "=r"(l), "=r"(h) : "l"(a)); return __uint_as_float(h);
}
__device__ __forceinline__ ull pack2(float l, float h) {
    ull d; asm("mov.b64 %0, {%1, %2};" : "=l"(d) : "r"(__float_as_uint(l)), "r"(__float_as_uint(h))); return d;
}
__device__ __forceinline__ uint32_t smem_u32(const void* p) {
    uint32_t a; asm("{ .reg .u64 t; cvta.to.shared.u64 t, %1; cvt.u32.u64 %0, t; }" : "=r"(a) : "l"(p));
    return a;
}
__device__ __forceinline__ void cp16(uint32_t dst, const void* src) {
    asm volatile("cp.async.cg.shared.global [%0], [%1], 16;" :: "r"(dst), "l"(src) : "memory");
}
#define CP_COMMIT() asm volatile("cp.async.commit_group;" ::: "memory")

// ---------------------------------------------------------------------------
// Kernel 0: WT[n][k] = W[k][n] (n<25), else 0
// ---------------------------------------------------------------------------
__global__ __launch_bounds__(256) void wt_prep(const float* __restrict__ W) {
    int i = blockIdx.x * 256 + threadIdx.x;
    if (i < 32 * Hn) {
        int n = i / Hn, k = i - n * Hn;
        g_wt[i] = (n < Ln) ? W[k * Ln + n] : 0.f;
    }
}

// ---------------------------------------------------------------------------
// Kernel 1: emissions = X @ W + b via mma.sync m16n8k8 tf32 (+ exp epilogue)
// grid 256 x 128 thr (4 warps). CTA = 128 rows. 24 K-chunks of 32, cp.async
// double-buffer. Warp tile 32x32.
// ---------------------------------------------------------------------------
#define SA0   0
#define SA1   18432
#define SB0   36864
#define SB1   41472
#define SBIAS 46080
#define GSMEM 46208

__global__ __launch_bounds__(128) void gemm_kernel(const float* __restrict__ X,
                                                   const float* __restrict__ bias,
                                                   float* __restrict__ em,
                                                   float* __restrict__ eem) {
    extern __shared__ char smem[];
    const uint32_t sb = smem_u32(smem);
    const int tid  = threadIdx.x;
    const int wid  = tid >> 5;
    const int lid  = tid & 31;
    const int grp  = lid >> 2;
    const int qd   = lid & 3;
    const int row0 = blockIdx.x * 128;
    const float* WT = g_wt;

    float* bias_s = (float*)(smem + SBIAS);
    if (tid < 32) bias_s[tid] = (tid < Ln) ? bias[tid] : 0.f;

    float c_[2][4][4];
#pragma unroll
    for (int mt = 0; mt < 2; ++mt)
#pragma unroll
        for (int nt = 0; nt < 4; ++nt)
#pragma unroll
            for (int r = 0; r < 4; ++r) c_[mt][nt][r] = 0.f;

    // ---- staging helper (A: 8 cp/thr, B: 2 cp/thr) ----
#define STAGE(CK, BUF)                                                          \
    {                                                                           \
        uint32_t ab = sb + ((BUF) ? SA1 : SA0);                                 \
        uint32_t bb = sb + ((BUF) ? SB1 : SB0);                                 \
        _Pragma("unroll")                                                       \
        for (int t = 0; t < 8; ++t) {                                           \
            int i = t * 128 + tid;                                              \
            int r = i >> 3, q = i & 7;                                          \
            cp16(ab + (r * 36 + q * 4) * 4,                                     \
                 X + (size_t)(row0 + r) * Hn + (CK) * 32 + q * 4);              \
        }                                                                       \
        _Pragma("unroll")                                                       \
        for (int t = 0; t < 2; ++t) {                                           \
            int i = t * 128 + tid;                                              \
            int n = i >> 3, q = i & 7;                                          \
            cp16(bb + (n * 36 + q * 4) * 4,                                     \
                 WT + n * Hn + (CK) * 32 + q * 4);                              \
        }                                                                       \
        CP_COMMIT();                                                            \
    }

    STAGE(0, 0)
    STAGE(1, 1)

    for (int ck = 0; ck < 24; ++ck) {
        if (ck < 23) asm volatile("cp.async.wait_group 1;" ::: "memory");
        else         asm volatile("cp.async.wait_group 0;" ::: "memory");
        __syncthreads();

        const int buf = ck & 1;
        const float* As = (const float*)(smem + (buf ? SA1 : SA0));
        const float* Bs = (const float*)(smem + (buf ? SB1 : SB0));

#pragma unroll
        for (int ks = 0; ks < 4; ++ks) {
            const int k0 = ks * 8;
            uint32_t a[2][4], b[4][2];
#pragma unroll
            for (int mt = 0; mt < 2; ++mt) {
                int r = wid * 32 + mt * 16 + grp;
                a[mt][0] = __float_as_uint(As[r * 36 + k0 + qd]);
                a[mt][1] = __float_as_uint(As[(r + 8) * 36 + k0 + qd]);
                a[mt][2] = __float_as_uint(As[r * 36 + k0 + qd + 4]);
                a[mt][3] = __float_as_uint(As[(r + 8) * 36 + k0 + qd + 4]);
            }
#pragma unroll
            for (int nt = 0; nt < 4; ++nt) {
                int n = nt * 8 + grp;
                b[nt][0] = __float_as_uint(Bs[n * 36 + k0 + qd]);
                b[nt][1] = __float_as_uint(Bs[n * 36 + k0 + qd + 4]);
            }
#pragma unroll
            for (int mt = 0; mt < 2; ++mt)
#pragma unroll
                for (int nt = 0; nt < 4; ++nt)
                    asm volatile(
                        "mma.sync.aligned.m16n8k8.row.col.f32.tf32.tf32.f32 "
                        "{%0,%1,%2,%3}, {%4,%5,%6,%7}, {%8,%9}, {%0,%1,%2,%3};"
                        : "+f"(c_[mt][nt][0]), "+f"(c_[mt][nt][1]),
                          "+f"(c_[mt][nt][2]), "+f"(c_[mt][nt][3])
                        : "r"(a[mt][0]), "r"(a[mt][1]), "r"(a[mt][2]), "r"(a[mt][3]),
                          "r"(b[nt][0]), "r"(b[nt][1]));
        }
        __syncthreads();
        if (ck + 2 < 24) STAGE(ck + 2, buf)
    }

    // ---- epilogue: bias add, pack em/exp(em) to smem, float4 to global ----
    float* pem = (float*)(smem + 0);
    float* pee = (float*)(smem + 12800);
#pragma unroll
    for (int mt = 0; mt < 2; ++mt) {
        int rb = wid * 32 + mt * 16 + grp;
#pragma unroll
        for (int nt = 0; nt < 4; ++nt) {
            int col = nt * 8 + 2 * qd;
            if (col < Ln) {
                float v0 = c_[mt][nt][0] + bias_s[col];
                float v2 = c_[mt][nt][2] + bias_s[col];
                pem[rb * Ln + col]       = v0;
                pem[(rb + 8) * Ln + col] = v2;
                pee[rb * Ln + col]       = __expf(v0);
                pee[(rb + 8) * Ln + col] = __expf(v2);
            }
            if (col + 1 < Ln) {
                float v1 = c_[mt][nt][1] + bias_s[col + 1];
                float v3 = c_[mt][nt][3] + bias_s[col + 1];
                pem[rb * Ln + col + 1]       = v1;
                pem[(rb + 8) * Ln + col + 1] = v3;
                pee[rb * Ln + col + 1]       = __expf(v1);
                pee[(rb + 8) * Ln + col + 1] = __expf(v3);
            }
        }
    }
    __syncthreads();
    {
        const float4* s0 = (const float4*)pem;
        const float4* s1 = (const float4*)pee;
        float4* g0 = (float4*)(em  + (size_t)row0 * Ln);
        float4* g1 = (float4*)(eem + (size_t)row0 * Ln);
#pragma unroll
        for (int t = 0; t < 7; ++t) {
            int i = t * 128 + tid;
            if (i < 800) { g0[i] = s0[i]; g1[i] = s1[i]; }
        }
    }
}

// ---------------------------------------------------------------------------
// Kernel 2: CRF. One warp per batch. Exp-domain scan; state broadcast via
// volatile smem (no syncwarp — converged warp, in-order LSU); branch-free
// power-of-2 renorm every 16 steps.
// ---------------------------------------------------------------------------
#define CRF_STEP(TL, TG)                                                        \
    {                                                                           \
        asm volatile("st.shared.b32 [%0], %1;"                                  \
                     :: "r"(pbase + 4u * (unsigned)j),                          \
                        "r"(__float_as_uint(p)) : "memory");                    \
        ull w0,w1,w2,w3,w4,w5,w6,w7,w8,w9,w10,w11,w12;                          \
        asm volatile("ld.shared.v2.u64 {%0,%1}, [%2];"                          \
                     : "=l"(w0), "=l"(w1) : "r"(pbase));                        \
        asm volatile("ld.shared.v2.u64 {%0,%1}, [%2];"                          \
                     : "=l"(w2), "=l"(w3) : "r"(pbase + 16));                   \
        asm volatile("ld.shared.v2.u64 {%0,%1}, [%2];"                          \
                     : "=l"(w4), "=l"(w5) : "r"(pbase + 32));                   \
        asm volatile("ld.shared.v2.u64 {%0,%1}, [%2];"                          \
                     : "=l"(w6), "=l"(w7) : "r"(pbase + 48));                   \
        asm volatile("ld.shared.v2.u64 {%0,%1}, [%2];"                          \
                     : "=l"(w8), "=l"(w9) : "r"(pbase + 64));                   \
        asm volatile("ld.shared.v2.u64 {%0,%1}, [%2];"                          \
                     : "=l"(w10), "=l"(w11) : "r"(pbase + 80));                 \
        asm volatile("ld.shared.u64 %0, [%1];"                                  \
                     : "=l"(w12) : "r"(pbase + 96));                            \
        ull A  = fma2(w0, et2[0], 0ull);                                        \
        ull Bq = fma2(w1, et2[1], 0ull);                                        \
        ull Cq = fma2(w2, et2[2], 0ull);                                        \
        ull Dq = fma2(w3, et2[3], 0ull);                                        \
        A  = fma2(w4, et2[4], A);   Bq = fma2(w5, et2[5], Bq);                  \
        Cq = fma2(w6, et2[6], Cq);  Dq = fma2(w7, et2[7], Dq);                  \
        A  = fma2(w8, et2[8], A);   Bq = fma2(w9, et2[9], Bq);                  \
        Cq = fma2(w10, et2[10], Cq); Dq = fma2(w11, et2[11], Dq);               \
        A  = fma2(w12, et2[12], A);                                             \
        A  = add2(A, Bq); Cq = add2(Cq, Dq); A = add2(A, Cq);                   \
        float q  = lo2(A) + hi2(A);                                             \
        float pn = q * ems[(TL) * Ln + jc];                                     \
        p = smask[TG] ? pn : p;                                                 \
    }

#define CRF_RENORM                                                              \
    {                                                                           \
        unsigned mx = __reduce_max_sync(0xffffffffu, __float_as_uint(p));       \
        int e = (int)(mx >> 23);                                                \
        float sc = __uint_as_float((unsigned)(253 - e) << 23);                  \
        p *= sc;                                                                \
        C += (float)(e - 126) * 0.6931471805599453f;                            \
    }

__global__ __launch_bounds__(32) void crf_kernel(const int* __restrict__ mask,
                                                 const int* __restrict__ labels,
                                                 const float* __restrict__ trans,
                                                 const float* __restrict__ start_t,
                                                 const float* __restrict__ end_t) {
    const int b  = blockIdx.x;
    const int j  = threadIdx.x;
    const int jc = (j < Ln) ? j : (Ln - 1);
    const bool lane_ok = (j < Ln);

    const float* emb  = g_em  + (size_t)b * Tn * Ln;
    const float* eemb = g_eem + (size_t)b * Tn * Ln;
    const int*   lb   = labels + b * Tn;

    __shared__ __align__(16) float pbuf[32];
    __shared__ float ems[64 * Ln];
    __shared__ int   smask[Tn];
    const uint32_t pbase = smem_u32(pbuf);

    for (int t = j; t < Tn; t += 32) smask[t] = mask[b * Tn + t];

    float numv = 0.f; int msum = 0;
    for (int t = j; t < Tn; t += 32) {
        int m = smask[t];
        msum += m;
        int lt = lb[t];
        if (t == 0)      numv += start_t[lt] + emb[lt];
        else if (m)      numv += trans[lb[t - 1] * Ln + lt] + emb[t * Ln + lt];
    }
#pragma unroll
    for (int off = 16; off; off >>= 1) {
        numv += __shfl_xor_sync(0xffffffffu, numv, off);
        msum += __shfl_xor_sync(0xffffffffu, msum, off);
    }

    ull et2[13];
#pragma unroll
    for (int i = 0; i < 13; ++i) {
        float lo = __expf(trans[(2 * i) * Ln + jc]);
        float hi = (2 * i + 1 < Ln) ? __expf(trans[(2 * i + 1) * Ln + jc]) : 0.f;
        et2[i] = pack2(lo, hi);
    }
    const float eend = __expf(end_t[jc]);

    float p = 0.f, C = 0.f;

    {
        __syncwarp();
        const float4* src = (const float4*)eemb;
        float4* dst = (float4*)ems;
#pragma unroll
        for (int i = 0; i < 13; ++i) { int idx = i * 32 + j; if (idx < 400) dst[idx] = src[idx]; }
        __syncwarp();

        p = __expf(start_t[jc]) * ems[jc];

#pragma unroll
        for (int u = 1; u < 16; ++u) CRF_STEP(u, u)
        CRF_RENORM
#pragma unroll
        for (int g = 1; g < 4; ++g) {
#pragma unroll
            for (int u = 0; u < 16; ++u) CRF_STEP(g * 16 + u, g * 16 + u)
            CRF_RENORM
        }
    }
    for (int c = 1; c < 8; ++c) {
        __syncwarp();
        const float4* src = (const float4*)(eemb + c * 64 * Ln);
        float4* dst = (float4*)ems;
#pragma unroll
        for (int i = 0; i < 13; ++i) { int idx = i * 32 + j; if (idx < 400) dst[idx] = src[idx]; }
        __syncwarp();
        const int tbase = c * 64;
#pragma unroll
        for (int g = 0; g < 4; ++g) {
#pragma unroll
            for (int u = 0; u < 16; ++u) CRF_STEP(g * 16 + u, tbase + g * 16 + u)
            CRF_RENORM
        }
    }

    float tot = lane_ok ? p * eend : 0.f;
#pragma unroll
    for (int off = 16; off; off >>= 1) tot += __shfl_xor_sync(0xffffffffu, tot, off);
    float denom = C + __logf(tot);

    if (j == 0) {
        int last = msum - 1;
        g_llh[b] = (numv + end_t[lb[last]]) - denom;
    }
}

// ---------------------------------------------------------------------------
__global__ __launch_bounds__(32) void finalize_kernel(float* __restrict__ out) {
    int tid = threadIdx.x;
    float s = g_llh[tid] + g_llh[tid + 32];
#pragma unroll
    for (int off = 16; off; off >>= 1) s += __shfl_xor_sync(0xffffffffu, s, off);
    if (tid == 0) out[0] = -s * (1.0f / 64.0f);
}

// ---------------------------------------------------------------------------
extern "C" void kernel_launch(void* const* d_in, const int* in_sizes, int n_in,
                              void* d_out, int out_size) {
    const float* X      = (const float*)d_in[0];
    const int*   mask   = (const int*)  d_in[1];
    const int*   labels = (const int*)  d_in[2];
    const float* W      = (const float*)d_in[3];
    const float* bias   = (const float*)d_in[4];
    const float* trans  = (const float*)d_in[5];
    const float* st     = (const float*)d_in[6];
    const float* en     = (const float*)d_in[7];
    float* out = (float*)d_out;

    float *emp = nullptr, *eemp = nullptr;
    cudaGetSymbolAddress((void**)&emp,  g_em);
    cudaGetSymbolAddress((void**)&eemp, g_eem);

    wt_prep<<<96, 256>>>(W);
    gemm_kernel<<<256, 128, GSMEM>>>(X, bias, emp, eemp);
    crf_kernel<<<Bn, 32>>>(mask, labels, trans, st, en);
    finalize_kernel<<<1, 32>>>(out);
}

// round 7
// speedup vs baseline: 5.9991x; 1.1450x over previous
#include <cuda_runtime.h>
#include <math.h>
#include <stdint.h>

#define Bn 64
#define Tn 512
#define Hn 768
#define Ln 25

__device__ __align__(16) float g_eem  [Bn * Tn * Ln];  // exp(emissions)
__device__ __align__(16) float g_emtag[Bn * Tn];       // em[row][label[row]]
__device__ float g_llh[Bn];
__device__ float g_wt [32 * Hn];                       // W^T zero-padded

typedef unsigned long long ull;

__device__ __forceinline__ ull fma2(ull a, ull b, ull c) {
    ull d; asm("fma.rn.f32x2 %0, %1, %2, %3;" : "=l"(d) : "l"(a), "l"(b), "l"(c)); return d;
}
__device__ __forceinline__ ull add2(ull a, ull b) {
    ull d; asm("add.rn.f32x2 %0, %1, %2;" : "=l"(d) : "l"(a), "l"(b)); return d;
}
__device__ __forceinline__ float lo2(ull a) {
    unsigned l, h; asm("mov.b64 {%0, %1}, %2;" : "=r"(l), "=r"(h) : "l"(a)); return __uint_as_float(l);
}
__device__ __forceinline__ float hi2(ull a) {
    unsigned l, h; asm("mov.b64 {%0, %1}, %2;" : "=r"(l), "=r"(h) : "l"(a)); return __uint_as_float(h);
}
__device__ __forceinline__ ull pack2(float l, float h) {
    ull d; asm("mov.b64 %0, {%1, %2};" : "=l"(d) : "r"(__float_as_uint(l)), "r"(__float_as_uint(h))); return d;
}
__device__ __forceinline__ uint32_t smem_u32(const void* p) {
    uint32_t a; asm("{ .reg .u64 t; cvta.to.shared.u64 t, %1; cvt.u32.u64 %0, t; }" : "=r"(a) : "l"(p));
    return a;
}
__device__ __forceinline__ void cp16(uint32_t dst, const void* src) {
    asm volatile("cp.async.cg.shared.global [%0], [%1], 16;" :: "r"(dst), "l"(src) : "memory");
}
#define CP_COMMIT() asm volatile("cp.async.commit_group;" ::: "memory")

// ---------------------------------------------------------------------------
// Kernel 0: WT[n][k] = W[k][n] (n<25) else 0
// ---------------------------------------------------------------------------
__global__ __launch_bounds__(256) void wt_prep(const float* __restrict__ W) {
    int i = blockIdx.x * 256 + threadIdx.x;
    if (i < 32 * Hn) {
        int n = i / Hn, k = i - n * Hn;
        g_wt[i] = (n < Ln) ? W[k * Ln + n] : 0.f;
    }
}

// ---------------------------------------------------------------------------
// Kernel 1: GEMM via mma.sync tf32. Epilogue: exp(em) + emtag only.
// ---------------------------------------------------------------------------
#define SA0   0
#define SA1   18432
#define SB0   36864
#define SB1   41472
#define SBIAS 46080
#define GSMEM 46208

__global__ __launch_bounds__(128) void gemm_kernel(const float* __restrict__ X,
                                                   const float* __restrict__ bias,
                                                   const int*   __restrict__ labels) {
    extern __shared__ char smem[];
    const uint32_t sb = smem_u32(smem);
    const int tid  = threadIdx.x;
    const int wid  = tid >> 5;
    const int lid  = tid & 31;
    const int grp  = lid >> 2;
    const int qd   = lid & 3;
    const int row0 = blockIdx.x * 128;
    const float* WT = g_wt;

    float* bias_s = (float*)(smem + SBIAS);
    if (tid < 32) bias_s[tid] = (tid < Ln) ? bias[tid] : 0.f;

    float c_[2][4][4];
#pragma unroll
    for (int mt = 0; mt < 2; ++mt)
#pragma unroll
        for (int nt = 0; nt < 4; ++nt)
#pragma unroll
            for (int r = 0; r < 4; ++r) c_[mt][nt][r] = 0.f;

#define STAGE(CK, BUF)                                                          \
    {                                                                           \
        uint32_t ab = sb + ((BUF) ? SA1 : SA0);                                 \
        uint32_t bb = sb + ((BUF) ? SB1 : SB0);                                 \
        _Pragma("unroll")                                                       \
        for (int t = 0; t < 8; ++t) {                                           \
            int i = t * 128 + tid;                                              \
            int r = i >> 3, q = i & 7;                                          \
            cp16(ab + (r * 36 + q * 4) * 4,                                     \
                 X + (size_t)(row0 + r) * Hn + (CK) * 32 + q * 4);              \
        }                                                                       \
        _Pragma("unroll")                                                       \
        for (int t = 0; t < 2; ++t) {                                           \
            int i = t * 128 + tid;                                              \
            int n = i >> 3, q = i & 7;                                          \
            cp16(bb + (n * 36 + q * 4) * 4,                                     \
                 WT + n * Hn + (CK) * 32 + q * 4);                              \
        }                                                                       \
        CP_COMMIT();                                                            \
    }

    STAGE(0, 0)
    STAGE(1, 1)

    for (int ck = 0; ck < 24; ++ck) {
        if (ck < 23) asm volatile("cp.async.wait_group 1;" ::: "memory");
        else         asm volatile("cp.async.wait_group 0;" ::: "memory");
        __syncthreads();

        const int buf = ck & 1;
        const float* As = (const float*)(smem + (buf ? SA1 : SA0));
        const float* Bs = (const float*)(smem + (buf ? SB1 : SB0));

#pragma unroll
        for (int ks = 0; ks < 4; ++ks) {
            const int k0 = ks * 8;
            uint32_t a[2][4], b[4][2];
#pragma unroll
            for (int mt = 0; mt < 2; ++mt) {
                int r = wid * 32 + mt * 16 + grp;
                a[mt][0] = __float_as_uint(As[r * 36 + k0 + qd]);
                a[mt][1] = __float_as_uint(As[(r + 8) * 36 + k0 + qd]);
                a[mt][2] = __float_as_uint(As[r * 36 + k0 + qd + 4]);
                a[mt][3] = __float_as_uint(As[(r + 8) * 36 + k0 + qd + 4]);
            }
#pragma unroll
            for (int nt = 0; nt < 4; ++nt) {
                int n = nt * 8 + grp;
                b[nt][0] = __float_as_uint(Bs[n * 36 + k0 + qd]);
                b[nt][1] = __float_as_uint(Bs[n * 36 + k0 + qd + 4]);
            }
#pragma unroll
            for (int mt = 0; mt < 2; ++mt)
#pragma unroll
                for (int nt = 0; nt < 4; ++nt)
                    asm volatile(
                        "mma.sync.aligned.m16n8k8.row.col.f32.tf32.tf32.f32 "
                        "{%0,%1,%2,%3}, {%4,%5,%6,%7}, {%8,%9}, {%0,%1,%2,%3};"
                        : "+f"(c_[mt][nt][0]), "+f"(c_[mt][nt][1]),
                          "+f"(c_[mt][nt][2]), "+f"(c_[mt][nt][3])
                        : "r"(a[mt][0]), "r"(a[mt][1]), "r"(a[mt][2]), "r"(a[mt][3]),
                          "r"(b[nt][0]), "r"(b[nt][1]));
        }
        __syncthreads();
        if (ck + 2 < 24) STAGE(ck + 2, buf)
    }

    // ---- epilogue: pack em + exp(em) to smem; write eem + emtag ----
    float* pem = (float*)(smem + 0);
    float* pee = (float*)(smem + 12800);
#pragma unroll
    for (int mt = 0; mt < 2; ++mt) {
        int rb = wid * 32 + mt * 16 + grp;
#pragma unroll
        for (int nt = 0; nt < 4; ++nt) {
            int col = nt * 8 + 2 * qd;
            if (col < Ln) {
                float v0 = c_[mt][nt][0] + bias_s[col];
                float v2 = c_[mt][nt][2] + bias_s[col];
                pem[rb * Ln + col]       = v0;
                pem[(rb + 8) * Ln + col] = v2;
                pee[rb * Ln + col]       = __expf(v0);
                pee[(rb + 8) * Ln + col] = __expf(v2);
            }
            if (col + 1 < Ln) {
                float v1 = c_[mt][nt][1] + bias_s[col + 1];
                float v3 = c_[mt][nt][3] + bias_s[col + 1];
                pem[rb * Ln + col + 1]       = v1;
                pem[(rb + 8) * Ln + col + 1] = v3;
                pee[rb * Ln + col + 1]       = __expf(v1);
                pee[(rb + 8) * Ln + col + 1] = __expf(v3);
            }
        }
    }
    __syncthreads();
    {
        int lab = labels[row0 + tid];
        g_emtag[row0 + tid] = pem[tid * Ln + lab];
        const float4* s1 = (const float4*)pee;
        float4* g1 = (float4*)(g_eem + (size_t)row0 * Ln);
#pragma unroll
        for (int t = 0; t < 7; ++t) {
            int i = t * 128 + tid;
            if (i < 800) g1[i] = s1[i];
        }
    }
}

// ---------------------------------------------------------------------------
// Kernel 2: CRF. cp.async double-buffered emission chunks; smem-broadcast
// matvec; branch-free power-of-2 renorm every 16 steps.
// ---------------------------------------------------------------------------
#define CRF_STEP(TL, TG)                                                        \
    {                                                                           \
        asm volatile("st.shared.b32 [%0], %1;"                                  \
                     :: "r"(pbase + 4u * (unsigned)j),                          \
                        "r"(__float_as_uint(p)) : "memory");                    \
        ull w0,w1,w2,w3,w4,w5,w6,w7,w8,w9,w10,w11,w12;                          \
        asm volatile("ld.shared.v2.u64 {%0,%1}, [%2];"                          \
                     : "=l"(w0), "=l"(w1) : "r"(pbase));                        \
        asm volatile("ld.shared.v2.u64 {%0,%1}, [%2];"                          \
                     : "=l"(w2), "=l"(w3) : "r"(pbase + 16));                   \
        asm volatile("ld.shared.v2.u64 {%0,%1}, [%2];"                          \
                     : "=l"(w4), "=l"(w5) : "r"(pbase + 32));                   \
        asm volatile("ld.shared.v2.u64 {%0,%1}, [%2];"                          \
                     : "=l"(w6), "=l"(w7) : "r"(pbase + 48));                   \
        asm volatile("ld.shared.v2.u64 {%0,%1}, [%2];"                          \
                     : "=l"(w8), "=l"(w9) : "r"(pbase + 64));                   \
        asm volatile("ld.shared.v2.u64 {%0,%1}, [%2];"                          \
                     : "=l"(w10), "=l"(w11) : "r"(pbase + 80));                 \
        asm volatile("ld.shared.u64 %0, [%1];"                                  \
                     : "=l"(w12) : "r"(pbase + 96));                            \
        ull A  = fma2(w0, et2[0], 0ull);                                        \
        ull Bq = fma2(w1, et2[1], 0ull);                                        \
        ull Cq = fma2(w2, et2[2], 0ull);                                        \
        ull Dq = fma2(w3, et2[3], 0ull);                                        \
        A  = fma2(w4, et2[4], A);   Bq = fma2(w5, et2[5], Bq);                  \
        Cq = fma2(w6, et2[6], Cq);  Dq = fma2(w7, et2[7], Dq);                  \
        A  = fma2(w8, et2[8], A);   Bq = fma2(w9, et2[9], Bq);                  \
        Cq = fma2(w10, et2[10], Cq); Dq = fma2(w11, et2[11], Dq);               \
        A  = fma2(w12, et2[12], A);                                             \
        A  = add2(A, Bq); Cq = add2(Cq, Dq); A = add2(A, Cq);                   \
        float q  = lo2(A) + hi2(A);                                             \
        float pn = q * emsb[(TL) * Ln + jc];                                    \
        p = smask[TG] ? pn : p;                                                 \
    }

#define CRF_RENORM                                                              \
    {                                                                           \
        unsigned mx = __reduce_max_sync(0xffffffffu, __float_as_uint(p));       \
        int e = (int)(mx >> 23);                                                \
        float sc = __uint_as_float((unsigned)(253 - e) << 23);                  \
        p *= sc;                                                                \
        C += (float)(e - 126) * 0.6931471805599453f;                            \
    }

#define STAGE_EMS(C, BUF)                                                       \
    {                                                                           \
        const float* srcp = eemb + (C) * 1600;                                  \
        uint32_t dstb = (BUF) ? emsb1 : emsb0;                                  \
        for (int i = j; i < 400; i += 32)                                       \
            cp16(dstb + 16u * (unsigned)i, srcp + 4 * i);                       \
        CP_COMMIT();                                                            \
    }

__global__ __launch_bounds__(32) void crf_kernel(const int* __restrict__ mask,
                                                 const int* __restrict__ labels,
                                                 const float* __restrict__ trans,
                                                 const float* __restrict__ start_t,
                                                 const float* __restrict__ end_t) {
    const int b  = blockIdx.x;
    const int j  = threadIdx.x;
    const int jc = (j < Ln) ? j : (Ln - 1);
    const bool lane_ok = (j < Ln);

    const float* eemb   = g_eem + (size_t)b * Tn * Ln;
    const float* emtagb = g_emtag + b * Tn;
    const int*   lb     = labels + b * Tn;

    __shared__ __align__(16) float ems2[2][1600];
    __shared__ __align__(16) float pbuf[32];
    __shared__ int smask[Tn];
    const uint32_t pbase = smem_u32(pbuf);
    const uint32_t emsb0 = smem_u32(ems2[0]);
    const uint32_t emsb1 = smem_u32(ems2[1]);

    // kick off first two chunks immediately
    STAGE_EMS(0, 0)
    STAGE_EMS(1, 1)

    for (int t = j; t < Tn; t += 32) smask[t] = mask[b * Tn + t];

    // ---- numerator from emtag (overlaps with cp.async fill) ----
    float numv = 0.f; int msum = 0;
    for (int t = j; t < Tn; t += 32) {
        int m = smask[t];
        msum += m;
        if (t == 0)  numv += start_t[lb[0]] + emtagb[0];
        else if (m)  numv += trans[lb[t - 1] * Ln + lb[t]] + emtagb[t];
    }
#pragma unroll
    for (int off = 16; off; off >>= 1) {
        numv += __shfl_xor_sync(0xffffffffu, numv, off);
        msum += __shfl_xor_sync(0xffffffffu, msum, off);
    }

    ull et2[13];
#pragma unroll
    for (int i = 0; i < 13; ++i) {
        float lo = __expf(trans[(2 * i) * Ln + jc]);
        float hi = (2 * i + 1 < Ln) ? __expf(trans[(2 * i + 1) * Ln + jc]) : 0.f;
        et2[i] = pack2(lo, hi);
    }
    const float eend = __expf(end_t[jc]);

    float p = 0.f, C = 0.f;

    for (int c = 0; c < 8; ++c) {
        if (c < 7) asm volatile("cp.async.wait_group 1;" ::: "memory");
        else       asm volatile("cp.async.wait_group 0;" ::: "memory");
        __syncwarp();
        const float* emsb = ems2[c & 1];
        const int tbase = c * 64;

        if (c == 0) {
            p = __expf(start_t[jc]) * emsb[jc];
#pragma unroll
            for (int u = 1; u < 16; ++u) CRF_STEP(u, u)
            CRF_RENORM
#pragma unroll
            for (int g = 1; g < 4; ++g) {
#pragma unroll
                for (int u = 0; u < 16; ++u) CRF_STEP(g * 16 + u, g * 16 + u)
                CRF_RENORM
            }
        } else {
#pragma unroll
            for (int g = 0; g < 4; ++g) {
#pragma unroll
                for (int u = 0; u < 16; ++u) CRF_STEP(g * 16 + u, tbase + g * 16 + u)
                CRF_RENORM
            }
        }
        // refill the buffer just consumed with chunk c+2
        if (c + 2 < 8) STAGE_EMS(c + 2, c & 1)
    }

    float tot = lane_ok ? p * eend : 0.f;
#pragma unroll
    for (int off = 16; off; off >>= 1) tot += __shfl_xor_sync(0xffffffffu, tot, off);
    float denom = C + __logf(tot);

    if (j == 0) {
        int last = msum - 1;
        g_llh[b] = (numv + end_t[lb[last]]) - denom;
    }
}

// ---------------------------------------------------------------------------
__global__ __launch_bounds__(32) void finalize_kernel(float* __restrict__ out) {
    int tid = threadIdx.x;
    float s = g_llh[tid] + g_llh[tid + 32];
#pragma unroll
    for (int off = 16; off; off >>= 1) s += __shfl_xor_sync(0xffffffffu, s, off);
    if (tid == 0) out[0] = -s * (1.0f / 64.0f);
}

// ---------------------------------------------------------------------------
extern "C" void kernel_launch(void* const* d_in, const int* in_sizes, int n_in,
                              void* d_out, int out_size) {
    const float* X      = (const float*)d_in[0];
    const int*   mask   = (const int*)  d_in[1];
    const int*   labels = (const int*)  d_in[2];
    const float* W      = (const float*)d_in[3];
    const float* bias   = (const float*)d_in[4];
    const float* trans  = (const float*)d_in[5];
    const float* st     = (const float*)d_in[6];
    const float* en     = (const float*)d_in[7];
    float* out = (float*)d_out;

    wt_prep<<<96, 256>>>(W);
    gemm_kernel<<<256, 128, GSMEM>>>(X, bias, labels);
    crf_kernel<<<Bn, 32>>>(mask, labels, trans, st, en);
    finalize_kernel<<<1, 32>>>(out);
}